// round 3
// baseline (speedup 1.0000x reference)
#include <cuda_runtime.h>
#include <cuda_bf16.h>
#include <math.h>

#define Bdim 2
#define Sdim 2048
#define Ddim 1024
#define Hdim 16
#define DHdim 64
#define NROWS (Bdim * Sdim)  // 4096

// Scratch (allocation-free contract: __device__ globals)
__device__ float g_q[NROWS * Ddim];
__device__ float g_k[NROWS * Ddim];
__device__ float g_v[NROWS * Ddim];
__device__ float g_ctx[NROWS * Ddim];
__device__ int   g_mask[NROWS];

// ---------------------------------------------------------------------------
// Mask dtype detection (jax bool -> int32 / uint8 / float32 on the wire).
// ---------------------------------------------------------------------------
__global__ void mask_expand_kernel(const void* __restrict__ mraw) {
    __shared__ int smode;
    if (threadIdx.x == 0) {
        const unsigned* w = (const unsigned*)mraw;
        int any_gt1 = 0, all_float = 1;
        for (int i = 0; i < 1024; ++i) {
            unsigned v = w[i];
            if (v > 1u) any_gt1 = 1;
            if (v != 0u && v != 0x3F800000u) all_float = 0;
        }
        smode = any_gt1 ? (all_float ? 2 : 1) : 0;  // 0=int32, 1=byte, 2=float
    }
    __syncthreads();
    int mode = smode;
    for (int i = threadIdx.x; i < NROWS; i += blockDim.x) {
        int v;
        if (mode == 1)      v = ((const unsigned char*)mraw)[i] != 0;
        else if (mode == 2) v = ((const float*)mraw)[i] != 0.0f;
        else                v = ((const int*)mraw)[i] != 0;
        g_mask[i] = v;
    }
}

// ---------------------------------------------------------------------------
// 3xTF32 tensor-core GEMM (mma.sync.m16n8k8). fp32 in/out, ~1e-6 precision.
//   x = hi + lo (each tf32); a*b ≈ ah*bh + ah*bl + al*bh
// ---------------------------------------------------------------------------
__device__ __forceinline__ void split_tf32(float x, unsigned& h, unsigned& l) {
    unsigned hi;
    asm("cvt.rna.tf32.f32 %0, %1;" : "=r"(hi) : "f"(x));
    float r = x - __uint_as_float(hi);
    unsigned lo;
    asm("cvt.rna.tf32.f32 %0, %1;" : "=r"(lo) : "f"(r));
    h = hi; l = lo;
}

__device__ __forceinline__ void mma_tf32(float (&c)[4], const unsigned (&a)[4],
                                         const unsigned (&b)[2]) {
    asm volatile(
        "mma.sync.aligned.m16n8k8.row.col.f32.tf32.tf32.f32 "
        "{%0,%1,%2,%3}, {%4,%5,%6,%7}, {%8,%9}, {%0,%1,%2,%3};\n"
        : "+f"(c[0]), "+f"(c[1]), "+f"(c[2]), "+f"(c[3])
        : "r"(a[0]), "r"(a[1]), "r"(a[2]), "r"(a[3]), "r"(b[0]), "r"(b[1]));
}

// BM=BN=64, BK=16, 256 threads = 8 warps in 4(m)x2(n); warp tile 16x32.
// Per-z offsets: off = (z/Hdim)*sb + (z%Hdim)*sh  (linear stride c: sb=16c, sh=c)
// TRANSB: B[k][n] = Bm[n*ldb + k]   (for Q@K^T)
// EPI: 0 = +bias[col]; 1 = *0.125 then key-mask (scores); 2 = plain
#define BMg 64
#define BNg 64
#define BKg 16

template <int TRANSB, int EPI>
__global__ __launch_bounds__(256) void gemm3x_kernel(
    const float* __restrict__ A, const float* __restrict__ Bm,
    float* __restrict__ C, const float* __restrict__ bias,
    int K, int lda, int ldb, int ldc,
    long sbA, long shA, long sbB, long shB, long sbC, long shC) {
    const int z = blockIdx.z;
    A  += (long)(z / Hdim) * sbA + (long)(z % Hdim) * shA;
    Bm += (long)(z / Hdim) * sbB + (long)(z % Hdim) * shB;
    C  += (long)(z / Hdim) * sbC + (long)(z % Hdim) * shC;

    __shared__ unsigned As_h[BKg][BMg + 4], As_l[BKg][BMg + 4];
    __shared__ unsigned Bs_h[BKg][BNg + 4], Bs_l[BKg][BNg + 4];

    const int t = threadIdx.x, lane = t & 31, warp = t >> 5;
    const int wm = (warp >> 1) * 16, wn = (warp & 1) * 32;
    const int row0 = blockIdx.y * BMg, col0 = blockIdx.x * BNg;

    const int ar = t >> 2, ac = (t & 3) * 4;     // A loader: row, k4
    const int br = t >> 4, bc = (t & 15) * 4;    // B loader (no trans): k, n4
    const int bn = t >> 2, bk = (t & 3) * 4;     // B loader (trans): n, k4

    float acc[4][4] = {};  // [n8][frag]

    for (int kk = 0; kk < K; kk += BKg) {
        // --- load + split A tile (64 x 16) ---
        float4 av = *reinterpret_cast<const float4*>(&A[(size_t)(row0 + ar) * lda + kk + ac]);
        {
            unsigned h, l;
            split_tf32(av.x, h, l); As_h[ac + 0][ar] = h; As_l[ac + 0][ar] = l;
            split_tf32(av.y, h, l); As_h[ac + 1][ar] = h; As_l[ac + 1][ar] = l;
            split_tf32(av.z, h, l); As_h[ac + 2][ar] = h; As_l[ac + 2][ar] = l;
            split_tf32(av.w, h, l); As_h[ac + 3][ar] = h; As_l[ac + 3][ar] = l;
        }
        // --- load + split B tile (16k x 64n), Bs[k][n] ---
        if (TRANSB) {
            float4 bv = *reinterpret_cast<const float4*>(&Bm[(size_t)(col0 + bn) * ldb + kk + bk]);
            unsigned h, l;
            split_tf32(bv.x, h, l); Bs_h[bk + 0][bn] = h; Bs_l[bk + 0][bn] = l;
            split_tf32(bv.y, h, l); Bs_h[bk + 1][bn] = h; Bs_l[bk + 1][bn] = l;
            split_tf32(bv.z, h, l); Bs_h[bk + 2][bn] = h; Bs_l[bk + 2][bn] = l;
            split_tf32(bv.w, h, l); Bs_h[bk + 3][bn] = h; Bs_l[bk + 3][bn] = l;
        } else {
            float4 bv = *reinterpret_cast<const float4*>(&Bm[(size_t)(kk + br) * ldb + col0 + bc]);
            unsigned h, l;
            split_tf32(bv.x, h, l); Bs_h[br][bc + 0] = h; Bs_l[br][bc + 0] = l;
            split_tf32(bv.y, h, l); Bs_h[br][bc + 1] = h; Bs_l[br][bc + 1] = l;
            split_tf32(bv.z, h, l); Bs_h[br][bc + 2] = h; Bs_l[br][bc + 2] = l;
            split_tf32(bv.w, h, l); Bs_h[br][bc + 3] = h; Bs_l[br][bc + 3] = l;
        }
        __syncthreads();

#pragma unroll
        for (int k8 = 0; k8 < BKg; k8 += 8) {
            const int kq = k8 + (lane & 3);
            const int mrow = wm + (lane >> 2);
            unsigned ah[4], al[4];
            ah[0] = As_h[kq][mrow];     ah[1] = As_h[kq][mrow + 8];
            ah[2] = As_h[kq + 4][mrow]; ah[3] = As_h[kq + 4][mrow + 8];
            al[0] = As_l[kq][mrow];     al[1] = As_l[kq][mrow + 8];
            al[2] = As_l[kq + 4][mrow]; al[3] = As_l[kq + 4][mrow + 8];
#pragma unroll
            for (int n8 = 0; n8 < 4; ++n8) {
                const int ncol = wn + n8 * 8 + (lane >> 2);
                unsigned bh[2], bl[2];
                bh[0] = Bs_h[kq][ncol]; bh[1] = Bs_h[kq + 4][ncol];
                bl[0] = Bs_l[kq][ncol]; bl[1] = Bs_l[kq + 4][ncol];
                mma_tf32(acc[n8], ah, bh);
                mma_tf32(acc[n8], ah, bl);
                mma_tf32(acc[n8], al, bh);
            }
        }
        __syncthreads();
    }

    // --- epilogue ---
    const int grow = row0 + wm + (lane >> 2);
#pragma unroll
    for (int n8 = 0; n8 < 4; ++n8) {
        const int gc = col0 + wn + n8 * 8 + (lane & 3) * 2;
#pragma unroll
        for (int f = 0; f < 4; ++f) {
            const int r = grow + (f >> 1) * 8;
            const int c = gc + (f & 1);
            float v = acc[n8][f];
            if (EPI == 0) {
                v += bias[c];
            } else if (EPI == 1) {
                v *= 0.125f;
                if (!g_mask[(z / Hdim) * Sdim + c]) v = -1e30f;
            }
            C[(size_t)r * ldc + c] = v;
        }
    }
}

// ---------------------------------------------------------------------------
// In-place row softmax over last axis (2048). One block (256 thr) per row.
// ---------------------------------------------------------------------------
__global__ __launch_bounds__(256)
void softmax_kernel(float* __restrict__ attn) {
    const size_t row = blockIdx.x;
    float* p = attn + row * (size_t)Sdim;
    const int t = threadIdx.x;
    const int lane = t & 31, warp = t >> 5;
    __shared__ float red[8];

    float v[8];
    float4 v0 = *reinterpret_cast<const float4*>(&p[t * 8]);
    float4 v1 = *reinterpret_cast<const float4*>(&p[t * 8 + 4]);
    v[0] = v0.x; v[1] = v0.y; v[2] = v0.z; v[3] = v0.w;
    v[4] = v1.x; v[5] = v1.y; v[6] = v1.z; v[7] = v1.w;

    float m = v[0];
#pragma unroll
    for (int i = 1; i < 8; ++i) m = fmaxf(m, v[i]);
#pragma unroll
    for (int off = 16; off > 0; off >>= 1) m = fmaxf(m, __shfl_xor_sync(0xFFFFFFFFu, m, off));
    if (lane == 0) red[warp] = m;
    __syncthreads();
    m = red[0];
#pragma unroll
    for (int i = 1; i < 8; ++i) m = fmaxf(m, red[i]);
    __syncthreads();

    float s = 0.0f;
#pragma unroll
    for (int i = 0; i < 8; ++i) { v[i] = __expf(v[i] - m); s += v[i]; }
#pragma unroll
    for (int off = 16; off > 0; off >>= 1) s += __shfl_xor_sync(0xFFFFFFFFu, s, off);
    if (lane == 0) red[warp] = s;
    __syncthreads();
    s = red[0];
#pragma unroll
    for (int i = 1; i < 8; ++i) s += red[i];
    float inv = 1.0f / s;

    float4 o0 = make_float4(v[0] * inv, v[1] * inv, v[2] * inv, v[3] * inv);
    float4 o1 = make_float4(v[4] * inv, v[5] * inv, v[6] * inv, v[7] * inv);
    *reinterpret_cast<float4*>(&p[t * 8])     = o0;
    *reinterpret_cast<float4*>(&p[t * 8 + 4]) = o1;
}

// ---------------------------------------------------------------------------
extern "C" void kernel_launch(void* const* d_in, const int* in_sizes, int n_in,
                              void* d_out, int out_size) {
    const float* qs = (const float*)d_in[0];
    const float* ks = (const float*)d_in[1];
    const float* vs = (const float*)d_in[2];
    const void*  mk = d_in[3];
    const float* Wq = (const float*)d_in[4];
    const float* bq = (const float*)d_in[5];
    const float* Wk = (const float*)d_in[6];
    const float* bk = (const float*)d_in[7];
    const float* Wv = (const float*)d_in[8];
    const float* bv = (const float*)d_in[9];
    const float* Wo = (const float*)d_in[10];
    const float* bo = (const float*)d_in[11];

    float* out  = (float*)d_out;
    float* attn = out + (size_t)NROWS * Ddim;  // (out, attn) concatenated

    float *dq, *dk, *dv, *dctx;
    cudaGetSymbolAddress((void**)&dq,   g_q);
    cudaGetSymbolAddress((void**)&dk,   g_k);
    cudaGetSymbolAddress((void**)&dv,   g_v);
    cudaGetSymbolAddress((void**)&dctx, g_ctx);

    dim3 blk(256);
    mask_expand_kernel<<<1, 256>>>(mk);

    const long SS = (long)Sdim * Sdim;
    const long SD = (long)Sdim * Ddim;

    // QKV projections: C[4096,1024] = A @ W + b
    dim3 gproj(Ddim / BNg, NROWS / BMg, 1);  // (16, 64)
    gemm3x_kernel<0, 0><<<gproj, blk>>>(qs, Wq, dq, bq, Ddim, Ddim, Ddim, Ddim,
                                        0, 0, 0, 0, 0, 0);
    gemm3x_kernel<0, 0><<<gproj, blk>>>(ks, Wk, dk, bk, Ddim, Ddim, Ddim, Ddim,
                                        0, 0, 0, 0, 0, 0);
    gemm3x_kernel<0, 0><<<gproj, blk>>>(vs, Wv, dv, bv, Ddim, Ddim, Ddim, Ddim,
                                        0, 0, 0, 0, 0, 0);

    // scores[z] = (Q_z @ K_z^T)/8, masked; z = b*H + h
    dim3 gsc(Sdim / BNg, Sdim / BMg, Bdim * Hdim);  // (32, 32, 32)
    gemm3x_kernel<1, 1><<<gsc, blk>>>(dq, dk, attn, nullptr,
                                      DHdim, Ddim, Ddim, Sdim,
                                      SD, DHdim, SD, DHdim, 16 * SS, SS);

    softmax_kernel<<<Bdim * Hdim * Sdim, 256>>>(attn);

    // ctx[z] = attn_z @ V_z   -> g_ctx in [B,S,D] layout
    dim3 gctx(1, Sdim / BMg, Bdim * Hdim);  // (1, 32, 32)
    gemm3x_kernel<0, 2><<<gctx, blk>>>(attn, dv, dctx, nullptr,
                                       Sdim, Sdim, Ddim, Ddim,
                                       16 * SS, SS, SD, DHdim, SD, DHdim);

    // output projection
    gemm3x_kernel<0, 0><<<gproj, blk>>>(dctx, Wo, out, bo, Ddim, Ddim, Ddim, Ddim,
                                        0, 0, 0, 0, 0, 0);
}

// round 4
// speedup vs baseline: 1.5321x; 1.5321x over previous
#include <cuda_runtime.h>
#include <cuda_bf16.h>
#include <math.h>

#define Bdim 2
#define Sdim 2048
#define Ddim 1024
#define Hdim 16
#define DHdim 64
#define NROWS (Bdim * Sdim)   // 4096
#define NROWS_A (32 * Sdim)   // B*H*S = 65536 attn rows

// Scratch (allocation-free contract)
__device__ float g_q[NROWS * Ddim];
__device__ float g_k[NROWS * Ddim];
__device__ float g_v[NROWS * Ddim];
__device__ float g_ctx[NROWS * Ddim];
__device__ int   g_mask[NROWS];
__device__ float g_part[(size_t)NROWS_A * 32];  // per-(row, key-block) exp partial sums
__device__ float g_inv[NROWS_A];                // 1/rowsum

// ---------------------------------------------------------------------------
__global__ void mask_expand_kernel(const void* __restrict__ mraw) {
    __shared__ int smode;
    if (threadIdx.x == 0) {
        const unsigned* w = (const unsigned*)mraw;
        int any_gt1 = 0, all_float = 1;
        for (int i = 0; i < 1024; ++i) {
            unsigned v = w[i];
            if (v > 1u) any_gt1 = 1;
            if (v != 0u && v != 0x3F800000u) all_float = 0;
        }
        smode = any_gt1 ? (all_float ? 2 : 1) : 0;  // 0=int32, 1=byte, 2=float
    }
    __syncthreads();
    int mode = smode;
    for (int i = threadIdx.x; i < NROWS; i += blockDim.x) {
        int v;
        if (mode == 1)      v = ((const unsigned char*)mraw)[i] != 0;
        else if (mode == 2) v = ((const float*)mraw)[i] != 0.0f;
        else                v = ((const int*)mraw)[i] != 0;
        g_mask[i] = v;
    }
}

// ---------------------------------------------------------------------------
// bf16 split helpers + mma/ldmatrix wrappers
// ---------------------------------------------------------------------------
__device__ __forceinline__ void split_bf(float x, unsigned short& h, unsigned short& l) {
    __nv_bfloat16 hb = __float2bfloat16_rn(x);
    float r = x - __bfloat162float(hb);
    __nv_bfloat16 lb = __float2bfloat16_rn(r);
    h = __bfloat16_as_ushort(hb);
    l = __bfloat16_as_ushort(lb);
}

__device__ __forceinline__ unsigned sptr(const void* p) {
    return (unsigned)__cvta_generic_to_shared(p);
}

__device__ __forceinline__ void ldmx4(unsigned (&r)[4], unsigned addr) {
    asm volatile("ldmatrix.sync.aligned.m8n8.x4.shared.b16 {%0,%1,%2,%3}, [%4];"
                 : "=r"(r[0]), "=r"(r[1]), "=r"(r[2]), "=r"(r[3]) : "r"(addr));
}

__device__ __forceinline__ void mma_bf16(float (&c)[4], const unsigned (&a)[4],
                                         const unsigned b0, const unsigned b1) {
    asm volatile(
        "mma.sync.aligned.m16n8k16.row.col.f32.bf16.bf16.f32 "
        "{%0,%1,%2,%3}, {%4,%5,%6,%7}, {%8,%9}, {%0,%1,%2,%3};\n"
        : "+f"(c[0]), "+f"(c[1]), "+f"(c[2]), "+f"(c[3])
        : "r"(a[0]), "r"(a[1]), "r"(a[2]), "r"(a[3]), "r"(b0), "r"(b1));
}

// ---------------------------------------------------------------------------
// bf16x2-split tensor-core GEMM. BM=128, BN=64, BK=32, 256 thr (8 warps 4m x 2n).
// BLOAD: 0 = B n-major in gmem (B[n][k], vector loads; scores Q@K^T)
//        1 = B k-major in gmem (B[k][n], transpose into smem; W / V)
// EPI:   0 = +bias[col]
//        1 = scores: e = mask ? exp(acc/8) : 0 ; write e; row partial sums
//        2 = ctx: A-loader scales attn rows by g_inv and writes normalized back
// ---------------------------------------------------------------------------
#define BMg 128
#define BNg 64
#define BKg 32
#define KP 40  // padded smem K stride (elems)

template <int BLOAD, int EPI>
__global__ __launch_bounds__(256) void bfgemm_kernel(
    const float* __restrict__ A, const float* __restrict__ Bm,
    float* __restrict__ C, const float* __restrict__ bias, float* Awb,
    int K, int lda, int ldb, int ldc,
    long sbA, long shA, long sbB, long shB, long sbC, long shC) {
    const int z = blockIdx.z;
    A  += (long)(z / Hdim) * sbA + (long)(z % Hdim) * shA;
    Bm += (long)(z / Hdim) * sbB + (long)(z % Hdim) * shB;
    C  += (long)(z / Hdim) * sbC + (long)(z % Hdim) * shC;
    if (EPI == 2) Awb += (long)(z / Hdim) * sbA + (long)(z % Hdim) * shA;

    __shared__ unsigned short As_h[BMg * KP], As_l[BMg * KP];
    __shared__ unsigned short Bs_h[BNg * KP], Bs_l[BNg * KP];
    __shared__ float rsum2[2 * BMg];

    const int t = threadIdx.x, lane = t & 31, warp = t >> 5;
    const int wm = (warp >> 1) * 32, wn = (warp & 1) * 32;
    const int row0 = blockIdx.y * BMg, col0 = blockIdx.x * BNg;

    // loader coords
    const int ar = t >> 1, ac0 = (t & 1) * 16;          // A: 4 float4 per thread
    const int bn = t >> 2, bc0 = (t & 3) * 8;           // B n-major: 2 float4
    const int bk = t >> 3, bn0 = (t & 7) * 8;           // B k-major: 2 float4 transposed

    float invv = 1.0f;
    if (EPI == 2) invv = g_inv[(size_t)z * Sdim + row0 + ar];

    // ldmatrix lane addressing
    const int lr  = lane & 7;
    const int lhi = (lane >> 3) & 1;
    const int lk  = (lane >> 4);

    float acc[2][4][4] = {};

    for (int kk = 0; kk < K; kk += BKg) {
        // ---- A tile (128 x 32) ----
#pragma unroll
        for (int i = 0; i < 4; ++i) {
            const size_t gidx = (size_t)(row0 + ar) * lda + kk + ac0 + i * 4;
            float4 v = *reinterpret_cast<const float4*>(&A[gidx]);
            if (EPI == 2) {
                v.x *= invv; v.y *= invv; v.z *= invv; v.w *= invv;
                *reinterpret_cast<float4*>(&Awb[gidx]) = v;
            }
            unsigned short h[4], l[4];
            split_bf(v.x, h[0], l[0]); split_bf(v.y, h[1], l[1]);
            split_bf(v.z, h[2], l[2]); split_bf(v.w, h[3], l[3]);
            const int s = ar * KP + ac0 + i * 4;
            *reinterpret_cast<uint2*>(&As_h[s]) = *reinterpret_cast<uint2*>(h);
            *reinterpret_cast<uint2*>(&As_l[s]) = *reinterpret_cast<uint2*>(l);
        }
        // ---- B tile -> Bs[n][k] ----
        if (BLOAD == 0) {
#pragma unroll
            for (int i = 0; i < 2; ++i) {
                float4 v = *reinterpret_cast<const float4*>(
                    &Bm[(size_t)(col0 + bn) * ldb + kk + bc0 + i * 4]);
                unsigned short h[4], l[4];
                split_bf(v.x, h[0], l[0]); split_bf(v.y, h[1], l[1]);
                split_bf(v.z, h[2], l[2]); split_bf(v.w, h[3], l[3]);
                const int s = bn * KP + bc0 + i * 4;
                *reinterpret_cast<uint2*>(&Bs_h[s]) = *reinterpret_cast<uint2*>(h);
                *reinterpret_cast<uint2*>(&Bs_l[s]) = *reinterpret_cast<uint2*>(l);
            }
        } else {
#pragma unroll
            for (int i = 0; i < 2; ++i) {
                float4 v = *reinterpret_cast<const float4*>(
                    &Bm[(size_t)(kk + bk) * ldb + col0 + bn0 + i * 4]);
                const float vv[4] = {v.x, v.y, v.z, v.w};
#pragma unroll
                for (int j = 0; j < 4; ++j) {
                    unsigned short h, l;
                    split_bf(vv[j], h, l);
                    Bs_h[(bn0 + i * 4 + j) * KP + bk] = h;
                    Bs_l[(bn0 + i * 4 + j) * KP + bk] = l;
                }
            }
        }
        __syncthreads();

#pragma unroll
        for (int ks = 0; ks < 2; ++ks) {
            const int kc = ks * 16 + lk * 8;
            unsigned ah[2][4], al[2][4];
#pragma unroll
            for (int mi = 0; mi < 2; ++mi) {
                const int rrow = wm + mi * 16 + lr + lhi * 8;
                ldmx4(ah[mi], sptr(&As_h[rrow * KP + kc]));
                ldmx4(al[mi], sptr(&As_l[rrow * KP + kc]));
            }
            unsigned bh[4][2], bl[4][2];
#pragma unroll
            for (int ni = 0; ni < 2; ++ni) {
                const int nrow = wn + ni * 16 + lr + lhi * 8;
                unsigned rh[4], rl[4];
                ldmx4(rh, sptr(&Bs_h[nrow * KP + kc]));
                ldmx4(rl, sptr(&Bs_l[nrow * KP + kc]));
                bh[ni * 2 + 0][0] = rh[0]; bh[ni * 2 + 0][1] = rh[2];
                bh[ni * 2 + 1][0] = rh[1]; bh[ni * 2 + 1][1] = rh[3];
                bl[ni * 2 + 0][0] = rl[0]; bl[ni * 2 + 0][1] = rl[2];
                bl[ni * 2 + 1][0] = rl[1]; bl[ni * 2 + 1][1] = rl[3];
            }
#pragma unroll
            for (int mi = 0; mi < 2; ++mi)
#pragma unroll
                for (int n8 = 0; n8 < 4; ++n8) {
                    mma_bf16(acc[mi][n8], ah[mi], bh[n8][0], bh[n8][1]);
                    mma_bf16(acc[mi][n8], ah[mi], bl[n8][0], bl[n8][1]);
                    mma_bf16(acc[mi][n8], al[mi], bh[n8][0], bh[n8][1]);
                }
        }
        __syncthreads();
    }

    // ---- epilogue ----
    const int maskbase = (z / Hdim) * Sdim;
#pragma unroll
    for (int mi = 0; mi < 2; ++mi)
#pragma unroll
        for (int n8 = 0; n8 < 4; ++n8)
#pragma unroll
            for (int f = 0; f < 4; ++f) {
                const int rl_ = wm + mi * 16 + (lane >> 2) + (f >> 1) * 8;
                const int cl_ = wn + n8 * 8 + (lane & 3) * 2 + (f & 1);
                const int gc = col0 + cl_;
                float v = acc[mi][n8][f];
                if (EPI == 0) {
                    v += bias[gc];
                } else if (EPI == 1) {
                    v = g_mask[maskbase + gc] ? __expf(v * 0.125f) : 0.0f;
                    acc[mi][n8][f] = v;
                }
                C[(size_t)(row0 + rl_) * ldc + gc] = v;
            }

    if (EPI == 1) {
        // deterministic per-row partial sums across this block's 64 key-cols
#pragma unroll
        for (int mi = 0; mi < 2; ++mi)
#pragma unroll
            for (int hf = 0; hf < 2; ++hf) {
                float s = 0.0f;
#pragma unroll
                for (int n8 = 0; n8 < 4; ++n8)
                    s += acc[mi][n8][hf * 2] + acc[mi][n8][hf * 2 + 1];
                s += __shfl_xor_sync(0xFFFFFFFFu, s, 1);
                s += __shfl_xor_sync(0xFFFFFFFFu, s, 2);
                if ((lane & 3) == 0)
                    rsum2[(warp & 1) * BMg + wm + mi * 16 + (lane >> 2) + hf * 8] = s;
            }
        __syncthreads();
        if (t < BMg) {
            float s = rsum2[t] + rsum2[BMg + t];
            g_part[((size_t)z * Sdim + row0 + t) * 32 + blockIdx.x] = s;
        }
    }
}

// ---------------------------------------------------------------------------
__global__ __launch_bounds__(256) void rowsum_kernel() {
    const int idx = blockIdx.x * 256 + threadIdx.x;  // 65536 rows
    float s = 0.0f;
#pragma unroll
    for (int i = 0; i < 32; ++i) s += g_part[(size_t)idx * 32 + i];
    g_inv[idx] = 1.0f / s;
}

// ---------------------------------------------------------------------------
extern "C" void kernel_launch(void* const* d_in, const int* in_sizes, int n_in,
                              void* d_out, int out_size) {
    const float* qs = (const float*)d_in[0];
    const float* ks = (const float*)d_in[1];
    const float* vs = (const float*)d_in[2];
    const void*  mk = d_in[3];
    const float* Wq = (const float*)d_in[4];
    const float* bq = (const float*)d_in[5];
    const float* Wk = (const float*)d_in[6];
    const float* bk = (const float*)d_in[7];
    const float* Wv = (const float*)d_in[8];
    const float* bv = (const float*)d_in[9];
    const float* Wo = (const float*)d_in[10];
    const float* bo = (const float*)d_in[11];

    float* out  = (float*)d_out;
    float* attn = out + (size_t)NROWS * Ddim;  // (out, attn) concatenated

    float *dq, *dk, *dv, *dctx;
    cudaGetSymbolAddress((void**)&dq,   g_q);
    cudaGetSymbolAddress((void**)&dk,   g_k);
    cudaGetSymbolAddress((void**)&dv,   g_v);
    cudaGetSymbolAddress((void**)&dctx, g_ctx);

    const long SS = (long)Sdim * Sdim;
    const long SD = (long)Sdim * Ddim;
    dim3 blk(256);

    mask_expand_kernel<<<1, 256>>>(mk);

    // QKV projections
    dim3 gproj(Ddim / BNg, NROWS / BMg, 1);  // (16, 32)
    bfgemm_kernel<1, 0><<<gproj, blk>>>(qs, Wq, dq, bq, nullptr,
                                        Ddim, Ddim, Ddim, Ddim, 0, 0, 0, 0, 0, 0);
    bfgemm_kernel<1, 0><<<gproj, blk>>>(ks, Wk, dk, bk, nullptr,
                                        Ddim, Ddim, Ddim, Ddim, 0, 0, 0, 0, 0, 0);
    bfgemm_kernel<1, 0><<<gproj, blk>>>(vs, Wv, dv, bv, nullptr,
                                        Ddim, Ddim, Ddim, Ddim, 0, 0, 0, 0, 0, 0);

    // scores -> exp(masked scores) into attn + row partial sums
    dim3 gsc(Sdim / BNg, Sdim / BMg, Bdim * Hdim);  // (32, 16, 32)
    bfgemm_kernel<0, 1><<<gsc, blk>>>(dq, dk, attn, nullptr, nullptr,
                                      DHdim, Ddim, Ddim, Sdim,
                                      SD, DHdim, SD, DHdim, 16 * SS, SS);

    rowsum_kernel<<<NROWS_A / 256, 256>>>();

    // ctx = softmax(attn) @ V ; normalizes attn in-place during A-load
    dim3 gctx(1, Sdim / BMg, Bdim * Hdim);  // (1, 16, 32)
    bfgemm_kernel<1, 2><<<gctx, blk>>>(attn, dv, dctx, nullptr, attn,
                                       Sdim, Sdim, Ddim, Ddim,
                                       16 * SS, SS, SD, DHdim, SD, DHdim);

    // output projection
    bfgemm_kernel<1, 0><<<gproj, blk>>>(dctx, Wo, out, bo, nullptr,
                                        Ddim, Ddim, Ddim, Ddim, 0, 0, 0, 0, 0, 0);
}

// round 5
// speedup vs baseline: 2.1486x; 1.4024x over previous
#include <cuda_runtime.h>
#include <cuda_bf16.h>
#include <math.h>

#define Bdim 2
#define Sdim 2048
#define Ddim 1024
#define Hdim 16
#define DHdim 64
#define NROWS (Bdim * Sdim)   // 4096
#define NROWS_A (32 * Sdim)   // 65536

typedef unsigned short ushortT;

// ---- persistent bf16 hi/lo planes (allocation-free contract) ----
__device__ ushortT g_iqh[NROWS * Ddim], g_iql[NROWS * Ddim];
__device__ ushortT g_ikh[NROWS * Ddim], g_ikl[NROWS * Ddim];
__device__ ushortT g_ivh[NROWS * Ddim], g_ivl[NROWS * Ddim];
__device__ ushortT g_qh[NROWS * Ddim],  g_ql[NROWS * Ddim];
__device__ ushortT g_kh[NROWS * Ddim],  g_kl[NROWS * Ddim];
__device__ ushortT g_vh[NROWS * Ddim],  g_vl[NROWS * Ddim];
__device__ ushortT g_vth[32 * DHdim * Sdim], g_vtl[32 * DHdim * Sdim];
__device__ ushortT g_wh[4 * Ddim * Ddim], g_wl[4 * Ddim * Ddim];  // W^T [n][k]
__device__ ushortT g_ch[NROWS * Ddim],  g_cl[NROWS * Ddim];
__device__ float g_part[(size_t)NROWS_A * 32];
__device__ float g_inv[NROWS_A];
__device__ int   g_mask[NROWS];

// ---------------------------------------------------------------------------
__global__ void mask_expand_kernel(const void* __restrict__ mraw) {
    __shared__ int smode;
    if (threadIdx.x == 0) {
        const unsigned* w = (const unsigned*)mraw;
        int any_gt1 = 0, all_float = 1;
        for (int i = 0; i < 1024; ++i) {
            unsigned v = w[i];
            if (v > 1u) any_gt1 = 1;
            if (v != 0u && v != 0x3F800000u) all_float = 0;
        }
        smode = any_gt1 ? (all_float ? 2 : 1) : 0;  // 0=int32, 1=byte, 2=float
    }
    __syncthreads();
    int mode = smode;
    for (int i = threadIdx.x; i < NROWS; i += blockDim.x) {
        int v;
        if (mode == 1)      v = ((const unsigned char*)mraw)[i] != 0;
        else if (mode == 2) v = ((const float*)mraw)[i] != 0.0f;
        else                v = ((const int*)mraw)[i] != 0;
        g_mask[i] = v;
    }
}

// ---------------------------------------------------------------------------
__device__ __forceinline__ void split_bf(float x, ushortT& h, ushortT& l) {
    __nv_bfloat16 hb = __float2bfloat16_rn(x);
    float r = x - __bfloat162float(hb);
    __nv_bfloat16 lb = __float2bfloat16_rn(r);
    h = __bfloat16_as_ushort(hb);
    l = __bfloat16_as_ushort(lb);
}
__device__ __forceinline__ unsigned sptr(const void* p) {
    return (unsigned)__cvta_generic_to_shared(p);
}
__device__ __forceinline__ void ldmx4(unsigned (&r)[4], unsigned addr) {
    asm volatile("ldmatrix.sync.aligned.m8n8.x4.shared.b16 {%0,%1,%2,%3}, [%4];"
                 : "=r"(r[0]), "=r"(r[1]), "=r"(r[2]), "=r"(r[3]) : "r"(addr));
}
__device__ __forceinline__ void mma_bf16(float (&c)[4], const unsigned (&a)[4],
                                         const unsigned b0, const unsigned b1) {
    asm volatile(
        "mma.sync.aligned.m16n8k16.row.col.f32.bf16.bf16.f32 "
        "{%0,%1,%2,%3}, {%4,%5,%6,%7}, {%8,%9}, {%0,%1,%2,%3};\n"
        : "+f"(c[0]), "+f"(c[1]), "+f"(c[2]), "+f"(c[3])
        : "r"(a[0]), "r"(a[1]), "r"(a[2]), "r"(a[3]), "r"(b0), "r"(b1));
}
__device__ __forceinline__ void cpasync16(unsigned s, const void* g) {
    asm volatile("cp.async.ca.shared.global [%0], [%1], 16;" :: "r"(s), "l"(g));
}
__device__ __forceinline__ void cpcommit() { asm volatile("cp.async.commit_group;"); }
template <int N>
__device__ __forceinline__ void cpwait() { asm volatile("cp.async.wait_group %0;" :: "n"(N)); }

// ---------------------------------------------------------------------------
// prep kernels
// ---------------------------------------------------------------------------
__global__ __launch_bounds__(256) void split_inputs_kernel(
    const float* __restrict__ q, const float* __restrict__ k, const float* __restrict__ v) {
    const float* src; ushortT *dh, *dl;
    if (blockIdx.z == 0)      { src = q; dh = g_iqh; dl = g_iql; }
    else if (blockIdx.z == 1) { src = k; dh = g_ikh; dl = g_ikl; }
    else                      { src = v; dh = g_ivh; dl = g_ivl; }
    size_t i = ((size_t)blockIdx.x * blockDim.x + threadIdx.x) * 4;
    float4 val = *reinterpret_cast<const float4*>(&src[i]);
    ushortT h[4], l[4];
    split_bf(val.x, h[0], l[0]); split_bf(val.y, h[1], l[1]);
    split_bf(val.z, h[2], l[2]); split_bf(val.w, h[3], l[3]);
    *reinterpret_cast<uint2*>(&dh[i]) = *reinterpret_cast<uint2*>(h);
    *reinterpret_cast<uint2*>(&dl[i]) = *reinterpret_cast<uint2*>(l);
}

__global__ __launch_bounds__(256) void wtrans_kernel(
    const float* __restrict__ w0, const float* __restrict__ w1,
    const float* __restrict__ w2, const float* __restrict__ w3) {
    const float* W = blockIdx.z == 0 ? w0 : blockIdx.z == 1 ? w1 : blockIdx.z == 2 ? w2 : w3;
    ushortT* Th = g_wh + (size_t)blockIdx.z * Ddim * Ddim;
    ushortT* Tl = g_wl + (size_t)blockIdx.z * Ddim * Ddim;
    __shared__ float tile[32][33];
    const int n0 = blockIdx.x * 32, k0 = blockIdx.y * 32;
    const int tx = threadIdx.x & 31, ty = threadIdx.x >> 5;
#pragma unroll
    for (int r = 0; r < 4; ++r)
        tile[ty + r * 8][tx] = W[(size_t)(k0 + ty + r * 8) * Ddim + n0 + tx];
    __syncthreads();
#pragma unroll
    for (int r = 0; r < 4; ++r) {
        float v = tile[tx][ty + r * 8];
        ushortT h, l; split_bf(v, h, l);
        Th[(size_t)(n0 + ty + r * 8) * Ddim + k0 + tx] = h;
        Tl[(size_t)(n0 + ty + r * 8) * Ddim + k0 + tx] = l;
    }
}

__global__ __launch_bounds__(256) void vtrans_kernel() {
    const int bh = blockIdx.z, b = bh >> 4, h = bh & 15;
    const int s0 = blockIdx.x * 32, d0 = blockIdx.y * 32;
    __shared__ ushortT th[32][34], tl[32][34];
    const int tx = threadIdx.x & 31, ty = threadIdx.x >> 5;
#pragma unroll
    for (int r = 0; r < 4; ++r) {
        size_t src = (size_t)(b * Sdim + s0 + ty + r * 8) * Ddim + h * DHdim + d0 + tx;
        th[ty + r * 8][tx] = g_vh[src];
        tl[ty + r * 8][tx] = g_vl[src];
    }
    __syncthreads();
#pragma unroll
    for (int r = 0; r < 4; ++r) {
        size_t dst = ((size_t)bh * DHdim + d0 + ty + r * 8) * Sdim + s0 + tx;
        g_vth[dst] = th[tx][ty + r * 8];
        g_vtl[dst] = tl[tx][ty + r * 8];
    }
}

// ---------------------------------------------------------------------------
// Main GEMM: bf16 2-term split (h+l), 3 MMA passes. BM=128 BN=64 BK=32, 256thr.
// ASRC: 0 = pre-split bf16 planes (cp.async double-buffered)
//       1 = fp32 A (ctx): register prefetch, scale by g_inv, write back, split
// EPI:  0 = +bias, split -> Ch/Cl     1 = exp/mask scores + partials (fp32 Cf)
//       2 = split -> Ch/Cl            3 = +bias fp32 -> Cf
// ---------------------------------------------------------------------------
#define BMg 128
#define BNg 64
#define BKg 32
#define KP 40

template <int ASRC, int EPI>
__global__ __launch_bounds__(256) void gemm2_kernel(
    const ushortT* __restrict__ Ah, const ushortT* __restrict__ Al,
    const float* __restrict__ Af, float* __restrict__ Awb,
    const ushortT* __restrict__ Bh, const ushortT* __restrict__ Bl,
    float* __restrict__ Cf, ushortT* __restrict__ Ch, ushortT* __restrict__ Cl,
    const float* __restrict__ bias,
    int K, int lda, int ldb, int ldc,
    long sbA, long shA, long sbB, long shB, long sbC, long shC) {
    const int z = blockIdx.z;
    const long aoff = (long)(z / Hdim) * sbA + (long)(z % Hdim) * shA;
    const long boff = (long)(z / Hdim) * sbB + (long)(z % Hdim) * shB;
    const long coff = (long)(z / Hdim) * sbC + (long)(z % Hdim) * shC;

    constexpr int ABUF = (ASRC == 0) ? 2 : 1;
    extern __shared__ char dynsmem[];
    ushortT* As_h = (ushortT*)dynsmem;
    ushortT* As_l = As_h + ABUF * BMg * KP;
    ushortT* Bs_h = As_l + ABUF * BMg * KP;
    ushortT* Bs_l = Bs_h + 2 * BNg * KP;
    float*  rsum2 = (float*)(Bs_l + 2 * BNg * KP);

    const int t = threadIdx.x, lane = t & 31, warp = t >> 5;
    const int wm = (warp >> 1) * 32, wn = (warp & 1) * 32;
    const int row0 = blockIdx.y * BMg, col0 = blockIdx.x * BNg;

    const int ar = t >> 1, ac0 = (t & 1) * 16;   // A: 128 rows x 32k
    const int brow = t >> 2, bcol = (t & 3) * 8; // B: 64 rows x 32k
    const int lr = lane & 7, lhi = (lane >> 3) & 1, lk = lane >> 4;

    float acc[2][4][4] = {};
    const int nt = K / BKg;

    float invv = 1.0f;
    if (ASRC == 1) invv = g_inv[(size_t)z * Sdim + row0 + ar];

    float4 areg[2][4];
    if (ASRC == 1) {
#pragma unroll
        for (int i = 0; i < 4; ++i)
            areg[0][i] = *reinterpret_cast<const float4*>(
                &Af[aoff + (size_t)(row0 + ar) * lda + ac0 + i * 4]);
    }
    // prologue: stage 0 loads
    if (ASRC == 0) {
#pragma unroll
        for (int i = 0; i < 2; ++i) {
            size_t g = aoff + (size_t)(row0 + ar) * lda + ac0 + i * 8;
            cpasync16(sptr(&As_h[ar * KP + ac0 + i * 8]), &Ah[g]);
            cpasync16(sptr(&As_l[ar * KP + ac0 + i * 8]), &Al[g]);
        }
    }
    {
        size_t gb = boff + (size_t)(col0 + brow) * ldb + bcol;
        cpasync16(sptr(&Bs_h[brow * KP + bcol]), &Bh[gb]);
        cpasync16(sptr(&Bs_l[brow * KP + bcol]), &Bl[gb]);
    }
    cpcommit();

    for (int tix = 0; tix < nt; ++tix) {
        const int cur = tix & 1, nxt = cur ^ 1;
        const int kk1 = (tix + 1) * BKg;
        if (tix + 1 < nt) {
            if (ASRC == 0) {
#pragma unroll
                for (int i = 0; i < 2; ++i) {
                    size_t g = aoff + (size_t)(row0 + ar) * lda + kk1 + ac0 + i * 8;
                    cpasync16(sptr(&As_h[nxt * BMg * KP + ar * KP + ac0 + i * 8]), &Ah[g]);
                    cpasync16(sptr(&As_l[nxt * BMg * KP + ar * KP + ac0 + i * 8]), &Al[g]);
                }
            }
            size_t gb = boff + (size_t)(col0 + brow) * ldb + kk1 + bcol;
            cpasync16(sptr(&Bs_h[nxt * BNg * KP + brow * KP + bcol]), &Bh[gb]);
            cpasync16(sptr(&Bs_l[nxt * BNg * KP + brow * KP + bcol]), &Bl[gb]);
        }
        cpcommit();

        if (ASRC == 1) {
            // scale, write back normalized attn, split into smem (single buffer)
#pragma unroll
            for (int i = 0; i < 4; ++i) {
                float4 v = areg[cur][i];
                v.x *= invv; v.y *= invv; v.z *= invv; v.w *= invv;
                size_t g = aoff + (size_t)(row0 + ar) * lda + tix * BKg + ac0 + i * 4;
                *reinterpret_cast<float4*>(&Awb[g]) = v;
                ushortT h[4], l[4];
                split_bf(v.x, h[0], l[0]); split_bf(v.y, h[1], l[1]);
                split_bf(v.z, h[2], l[2]); split_bf(v.w, h[3], l[3]);
                const int s = ar * KP + ac0 + i * 4;
                *reinterpret_cast<uint2*>(&As_h[s]) = *reinterpret_cast<uint2*>(h);
                *reinterpret_cast<uint2*>(&As_l[s]) = *reinterpret_cast<uint2*>(l);
            }
            if (tix + 1 < nt) {
#pragma unroll
                for (int i = 0; i < 4; ++i)
                    areg[nxt][i] = *reinterpret_cast<const float4*>(
                        &Af[aoff + (size_t)(row0 + ar) * lda + kk1 + ac0 + i * 4]);
            }
        }

        cpwait<1>();
        __syncthreads();

        const int asb = (ASRC == 0) ? cur * BMg * KP : 0;
        const int bsb = cur * BNg * KP;
#pragma unroll
        for (int ks = 0; ks < 2; ++ks) {
            const int kc = ks * 16 + lk * 8;
            unsigned ah[2][4], al2[2][4];
#pragma unroll
            for (int mi = 0; mi < 2; ++mi) {
                const int rrow = wm + mi * 16 + lr + lhi * 8;
                ldmx4(ah[mi],  sptr(&As_h[asb + rrow * KP + kc]));
                ldmx4(al2[mi], sptr(&As_l[asb + rrow * KP + kc]));
            }
            unsigned bh[4][2], bl[4][2];
#pragma unroll
            for (int ni = 0; ni < 2; ++ni) {
                const int nrow = wn + ni * 16 + lr + lhi * 8;
                unsigned rh[4], rl[4];
                ldmx4(rh, sptr(&Bs_h[bsb + nrow * KP + kc]));
                ldmx4(rl, sptr(&Bs_l[bsb + nrow * KP + kc]));
                bh[ni * 2 + 0][0] = rh[0]; bh[ni * 2 + 0][1] = rh[2];
                bh[ni * 2 + 1][0] = rh[1]; bh[ni * 2 + 1][1] = rh[3];
                bl[ni * 2 + 0][0] = rl[0]; bl[ni * 2 + 0][1] = rl[2];
                bl[ni * 2 + 1][0] = rl[1]; bl[ni * 2 + 1][1] = rl[3];
            }
#pragma unroll
            for (int mi = 0; mi < 2; ++mi)
#pragma unroll
                for (int n8 = 0; n8 < 4; ++n8) {
                    mma_bf16(acc[mi][n8], ah[mi],  bh[n8][0], bh[n8][1]);
                    mma_bf16(acc[mi][n8], ah[mi],  bl[n8][0], bl[n8][1]);
                    mma_bf16(acc[mi][n8], al2[mi], bh[n8][0], bh[n8][1]);
                }
        }
        __syncthreads();
    }

    // ---- epilogue ----
    const int maskbase = (z / Hdim) * Sdim;
#pragma unroll
    for (int mi = 0; mi < 2; ++mi)
#pragma unroll
        for (int n8 = 0; n8 < 4; ++n8) {
            const int rl0 = wm + mi * 16 + (lane >> 2);
            const int cl0 = wn + n8 * 8 + (lane & 3) * 2;
#pragma unroll
            for (int hf = 0; hf < 2; ++hf) {
                const int r = row0 + rl0 + hf * 8;
                const int c = col0 + cl0;
                float v0 = acc[mi][n8][hf * 2], v1 = acc[mi][n8][hf * 2 + 1];
                if (EPI == 0 || EPI == 3) { v0 += bias[c]; v1 += bias[c + 1]; }
                if (EPI == 1) {
                    v0 = g_mask[maskbase + c]     ? __expf(v0 * 0.125f) : 0.0f;
                    v1 = g_mask[maskbase + c + 1] ? __expf(v1 * 0.125f) : 0.0f;
                    acc[mi][n8][hf * 2] = v0; acc[mi][n8][hf * 2 + 1] = v1;
                }
                size_t ci = coff + (size_t)r * ldc + c;
                if (EPI == 1 || EPI == 3) {
                    *reinterpret_cast<float2*>(&Cf[ci]) = make_float2(v0, v1);
                } else {
                    ushortT h0, l0, h1, l1;
                    split_bf(v0, h0, l0); split_bf(v1, h1, l1);
                    *reinterpret_cast<unsigned*>(&Ch[ci]) = (unsigned)h0 | ((unsigned)h1 << 16);
                    *reinterpret_cast<unsigned*>(&Cl[ci]) = (unsigned)l0 | ((unsigned)l1 << 16);
                }
            }
        }

    if (EPI == 1) {
#pragma unroll
        for (int mi = 0; mi < 2; ++mi)
#pragma unroll
            for (int hf = 0; hf < 2; ++hf) {
                float s = 0.0f;
#pragma unroll
                for (int n8 = 0; n8 < 4; ++n8)
                    s += acc[mi][n8][hf * 2] + acc[mi][n8][hf * 2 + 1];
                s += __shfl_xor_sync(0xFFFFFFFFu, s, 1);
                s += __shfl_xor_sync(0xFFFFFFFFu, s, 2);
                if ((lane & 3) == 0)
                    rsum2[(warp & 1) * BMg + wm + mi * 16 + (lane >> 2) + hf * 8] = s;
            }
        __syncthreads();
        if (t < BMg) {
            float s = rsum2[t] + rsum2[BMg + t];
            g_part[((size_t)z * Sdim + row0 + t) * 32 + blockIdx.x] = s;
        }
    }
}

// ---------------------------------------------------------------------------
__global__ __launch_bounds__(256) void rowsum_kernel() {
    const int idx = blockIdx.x * 256 + threadIdx.x;
    float s = 0.0f;
#pragma unroll
    for (int i = 0; i < 32; ++i) s += g_part[(size_t)idx * 32 + i];
    g_inv[idx] = 1.0f / s;
}

// ---------------------------------------------------------------------------
extern "C" void kernel_launch(void* const* d_in, const int* in_sizes, int n_in,
                              void* d_out, int out_size) {
    const float* qs = (const float*)d_in[0];
    const float* ks = (const float*)d_in[1];
    const float* vs = (const float*)d_in[2];
    const void*  mk = d_in[3];
    const float* Wq = (const float*)d_in[4];
    const float* bq = (const float*)d_in[5];
    const float* Wk = (const float*)d_in[6];
    const float* bk = (const float*)d_in[7];
    const float* Wv = (const float*)d_in[8];
    const float* bv = (const float*)d_in[9];
    const float* Wo = (const float*)d_in[10];
    const float* bo = (const float*)d_in[11];

    float* out  = (float*)d_out;
    float* attn = out + (size_t)NROWS * Ddim;

    ushortT *iqh, *iql, *ikh, *ikl, *ivh, *ivl, *qh, *ql, *kh, *kl, *vth, *vtl,
            *wh, *wl, *ch, *cl;
    cudaGetSymbolAddress((void**)&iqh, g_iqh); cudaGetSymbolAddress((void**)&iql, g_iql);
    cudaGetSymbolAddress((void**)&ikh, g_ikh); cudaGetSymbolAddress((void**)&ikl, g_ikl);
    cudaGetSymbolAddress((void**)&ivh, g_ivh); cudaGetSymbolAddress((void**)&ivl, g_ivl);
    cudaGetSymbolAddress((void**)&qh,  g_qh);  cudaGetSymbolAddress((void**)&ql,  g_ql);
    cudaGetSymbolAddress((void**)&kh,  g_kh);  cudaGetSymbolAddress((void**)&kl,  g_kl);
    ushortT *vh, *vl;
    cudaGetSymbolAddress((void**)&vh,  g_vh);  cudaGetSymbolAddress((void**)&vl,  g_vl);
    cudaGetSymbolAddress((void**)&vth, g_vth); cudaGetSymbolAddress((void**)&vtl, g_vtl);
    cudaGetSymbolAddress((void**)&wh,  g_wh);  cudaGetSymbolAddress((void**)&wl,  g_wl);
    cudaGetSymbolAddress((void**)&ch,  g_ch);  cudaGetSymbolAddress((void**)&cl,  g_cl);

    const long SS = (long)Sdim * Sdim;
    const long SD = (long)Sdim * Ddim;
    const size_t WSZ = (size_t)Ddim * Ddim;
    dim3 blk(256);

    const int SMEM_B0 = (2 * 2 * BMg * KP + 4 * BNg * KP) * 2 + 2 * BMg * 4;  // 62464
    const int SMEM_B1 = (2 * 1 * BMg * KP + 4 * BNg * KP) * 2 + 2 * BMg * 4;  // 41984
    cudaFuncSetAttribute(gemm2_kernel<0, 0>, cudaFuncAttributeMaxDynamicSharedMemorySize, SMEM_B0);
    cudaFuncSetAttribute(gemm2_kernel<0, 1>, cudaFuncAttributeMaxDynamicSharedMemorySize, SMEM_B0);
    cudaFuncSetAttribute(gemm2_kernel<1, 2>, cudaFuncAttributeMaxDynamicSharedMemorySize, SMEM_B1);
    cudaFuncSetAttribute(gemm2_kernel<0, 3>, cudaFuncAttributeMaxDynamicSharedMemorySize, SMEM_B0);

    mask_expand_kernel<<<1, 256>>>(mk);
    split_inputs_kernel<<<dim3(4096, 1, 3), blk>>>(qs, ks, vs);
    wtrans_kernel<<<dim3(32, 32, 4), blk>>>(Wq, Wk, Wv, Wo);

    // projections: planes = input_planes @ Wt + bias
    dim3 gproj(Ddim / BNg, NROWS / BMg, 1);  // (16, 32)
    gemm2_kernel<0, 0><<<gproj, blk, SMEM_B0>>>(
        iqh, iql, nullptr, nullptr, wh + 0 * WSZ, wl + 0 * WSZ,
        nullptr, qh, ql, bq, Ddim, Ddim, Ddim, Ddim, 0, 0, 0, 0, 0, 0);
    gemm2_kernel<0, 0><<<gproj, blk, SMEM_B0>>>(
        ikh, ikl, nullptr, nullptr, wh + 1 * WSZ, wl + 1 * WSZ,
        nullptr, kh, kl, bk, Ddim, Ddim, Ddim, Ddim, 0, 0, 0, 0, 0, 0);
    gemm2_kernel<0, 0><<<gproj, blk, SMEM_B0>>>(
        ivh, ivl, nullptr, nullptr, wh + 2 * WSZ, wl + 2 * WSZ,
        nullptr, vh, vl, bv, Ddim, Ddim, Ddim, Ddim, 0, 0, 0, 0, 0, 0);

    vtrans_kernel<<<dim3(Sdim / 32, DHdim / 32, 32), blk>>>();

    // scores -> exp(masked)/partials into attn
    dim3 gsc(Sdim / BNg, Sdim / BMg, Bdim * Hdim);  // (32, 16, 32)
    gemm2_kernel<0, 1><<<gsc, blk, SMEM_B0>>>(
        qh, ql, nullptr, nullptr, kh, kl, attn, nullptr, nullptr, nullptr,
        DHdim, Ddim, Ddim, Sdim,
        (long)Sdim * Ddim, DHdim, (long)Sdim * Ddim, DHdim, 16 * SS, SS);

    rowsum_kernel<<<NROWS_A / 256, 256>>>();

    // ctx = softmax(attn) @ V ; normalizes attn in-place; emits ctx planes
    dim3 gctx(1, Sdim / BMg, Bdim * Hdim);  // (1, 16, 32)
    gemm2_kernel<1, 2><<<gctx, blk, SMEM_B1>>>(
        nullptr, nullptr, attn, attn, vth, vtl, nullptr, ch, cl, nullptr,
        Sdim, Sdim, Sdim, Ddim,
        16 * SS, SS, (long)16 * DHdim * Sdim, (long)DHdim * Sdim,
        (long)Sdim * Ddim, DHdim);

    // output projection -> fp32 out
    gemm2_kernel<0, 3><<<gproj, blk, SMEM_B0>>>(
        ch, cl, nullptr, nullptr, wh + 3 * WSZ, wl + 3 * WSZ,
        out, nullptr, nullptr, bo, Ddim, Ddim, Ddim, Ddim, 0, 0, 0, 0, 0, 0);
}

// round 7
// speedup vs baseline: 2.7341x; 1.2725x over previous
#include <cuda_runtime.h>
#include <cuda_bf16.h>
#include <math.h>

#define Bdim 2
#define Sdim 2048
#define Ddim 1024
#define Hdim 16
#define DHdim 64
#define NROWS (Bdim * Sdim)   // 4096
#define NROWS_A (32 * Sdim)   // 65536

typedef unsigned short ushortT;

// ---- persistent bf16 hi/lo planes (allocation-free contract) ----
__device__ ushortT g_iqh[NROWS * Ddim], g_iql[NROWS * Ddim];
__device__ ushortT g_ikh[NROWS * Ddim], g_ikl[NROWS * Ddim];
__device__ ushortT g_ivh[NROWS * Ddim], g_ivl[NROWS * Ddim];
__device__ ushortT g_qh[NROWS * Ddim],  g_ql[NROWS * Ddim];
__device__ ushortT g_kh[NROWS * Ddim],  g_kl[NROWS * Ddim];
__device__ ushortT g_vh[NROWS * Ddim],  g_vl[NROWS * Ddim];
__device__ ushortT g_vth[32 * DHdim * Sdim], g_vtl[32 * DHdim * Sdim];
__device__ ushortT g_wh[4 * Ddim * Ddim], g_wl[4 * Ddim * Ddim];  // W^T [n][k]
__device__ ushortT g_ch[NROWS * Ddim],  g_cl[NROWS * Ddim];
__device__ float g_part[(size_t)NROWS_A * 16];
__device__ float g_inv[NROWS_A];
__device__ int   g_mask[NROWS];

// ---------------------------------------------------------------------------
__global__ void mask_expand_kernel(const void* __restrict__ mraw) {
    __shared__ int smode;
    if (threadIdx.x == 0) {
        const unsigned* w = (const unsigned*)mraw;
        int any_gt1 = 0, all_float = 1;
        for (int i = 0; i < 1024; ++i) {
            unsigned v = w[i];
            if (v > 1u) any_gt1 = 1;
            if (v != 0u && v != 0x3F800000u) all_float = 0;
        }
        smode = any_gt1 ? (all_float ? 2 : 1) : 0;  // 0=int32, 1=byte, 2=float
    }
    __syncthreads();
    int mode = smode;
    for (int i = threadIdx.x; i < NROWS; i += blockDim.x) {
        int v;
        if (mode == 1)      v = ((const unsigned char*)mraw)[i] != 0;
        else if (mode == 2) v = ((const float*)mraw)[i] != 0.0f;
        else                v = ((const int*)mraw)[i] != 0;
        g_mask[i] = v;
    }
}

// ---------------------------------------------------------------------------
__device__ __forceinline__ void split_bf(float x, ushortT& h, ushortT& l) {
    __nv_bfloat16 hb = __float2bfloat16_rn(x);
    float r = x - __bfloat162float(hb);
    __nv_bfloat16 lb = __float2bfloat16_rn(r);
    h = __bfloat16_as_ushort(hb);
    l = __bfloat16_as_ushort(lb);
}
__device__ __forceinline__ void ldmx4(unsigned (&r)[4], unsigned addr) {
    asm volatile("ldmatrix.sync.aligned.m8n8.x4.shared.b16 {%0,%1,%2,%3}, [%4];"
                 : "=r"(r[0]), "=r"(r[1]), "=r"(r[2]), "=r"(r[3]) : "r"(addr));
}
__device__ __forceinline__ void mma_bf16(float (&c)[4], const unsigned (&a)[4],
                                         const unsigned b0, const unsigned b1) {
    asm volatile(
        "mma.sync.aligned.m16n8k16.row.col.f32.bf16.bf16.f32 "
        "{%0,%1,%2,%3}, {%4,%5,%6,%7}, {%8,%9}, {%0,%1,%2,%3};\n"
        : "+f"(c[0]), "+f"(c[1]), "+f"(c[2]), "+f"(c[3])
        : "r"(a[0]), "r"(a[1]), "r"(a[2]), "r"(a[3]), "r"(b0), "r"(b1));
}
__device__ __forceinline__ void cpasync16(unsigned s, const void* g) {
    asm volatile("cp.async.ca.shared.global [%0], [%1], 16;" :: "r"(s), "l"(g));
}
__device__ __forceinline__ void cpcommit() { asm volatile("cp.async.commit_group;"); }
template <int N>
__device__ __forceinline__ void cpwait() {
    asm volatile("cp.async.wait_group %0;" :: "n"(N) : "memory");
}

// ---------------------------------------------------------------------------
// prep kernels
// ---------------------------------------------------------------------------
__global__ __launch_bounds__(256) void split_inputs_kernel(
    const float* __restrict__ q, const float* __restrict__ k, const float* __restrict__ v) {
    const float* src; ushortT *dh, *dl;
    if (blockIdx.z == 0)      { src = q; dh = g_iqh; dl = g_iql; }
    else if (blockIdx.z == 1) { src = k; dh = g_ikh; dl = g_ikl; }
    else                      { src = v; dh = g_ivh; dl = g_ivl; }
    size_t i = ((size_t)blockIdx.x * blockDim.x + threadIdx.x) * 4;
    float4 val = *reinterpret_cast<const float4*>(&src[i]);
    ushortT h[4], l[4];
    split_bf(val.x, h[0], l[0]); split_bf(val.y, h[1], l[1]);
    split_bf(val.z, h[2], l[2]); split_bf(val.w, h[3], l[3]);
    *reinterpret_cast<uint2*>(&dh[i]) = *reinterpret_cast<uint2*>(h);
    *reinterpret_cast<uint2*>(&dl[i]) = *reinterpret_cast<uint2*>(l);
}

__global__ __launch_bounds__(256) void wtrans_kernel(
    const float* __restrict__ w0, const float* __restrict__ w1,
    const float* __restrict__ w2, const float* __restrict__ w3) {
    const float* W = blockIdx.z == 0 ? w0 : blockIdx.z == 1 ? w1 : blockIdx.z == 2 ? w2 : w3;
    ushortT* Th = g_wh + (size_t)blockIdx.z * Ddim * Ddim;
    ushortT* Tl = g_wl + (size_t)blockIdx.z * Ddim * Ddim;
    __shared__ float tile[32][33];
    const int n0 = blockIdx.x * 32, k0 = blockIdx.y * 32;
    const int tx = threadIdx.x & 31, ty = threadIdx.x >> 5;
#pragma unroll
    for (int r = 0; r < 4; ++r)
        tile[ty + r * 8][tx] = W[(size_t)(k0 + ty + r * 8) * Ddim + n0 + tx];
    __syncthreads();
#pragma unroll
    for (int r = 0; r < 4; ++r) {
        float v = tile[tx][ty + r * 8];
        ushortT h, l; split_bf(v, h, l);
        Th[(size_t)(n0 + ty + r * 8) * Ddim + k0 + tx] = h;
        Tl[(size_t)(n0 + ty + r * 8) * Ddim + k0 + tx] = l;
    }
}

__global__ __launch_bounds__(256) void vtrans_kernel() {
    const int bh = blockIdx.z, b = bh >> 4, h = bh & 15;
    const int s0 = blockIdx.x * 32, d0 = blockIdx.y * 32;
    __shared__ ushortT th[32][34], tl[32][34];
    const int tx = threadIdx.x & 31, ty = threadIdx.x >> 5;
#pragma unroll
    for (int r = 0; r < 4; ++r) {
        size_t src = (size_t)(b * Sdim + s0 + ty + r * 8) * Ddim + h * DHdim + d0 + tx;
        th[ty + r * 8][tx] = g_vh[src];
        tl[ty + r * 8][tx] = g_vl[src];
    }
    __syncthreads();
#pragma unroll
    for (int r = 0; r < 4; ++r) {
        size_t dst = ((size_t)bh * DHdim + d0 + ty + r * 8) * Sdim + s0 + tx;
        g_vth[dst] = th[tx][ty + r * 8];
        g_vtl[dst] = tl[tx][ty + r * 8];
    }
}

__global__ __launch_bounds__(256) void rowsum_kernel() {
    const int idx = blockIdx.x * 256 + threadIdx.x;
    float s = 0.0f;
#pragma unroll
    for (int i = 0; i < 16; ++i) s += g_part[(size_t)idx * 16 + i];
    g_inv[idx] = 1.0f / s;
}

// ---------------------------------------------------------------------------
// bf16 2-term-split tensor-core GEMM (hh + hl + lh). BM=128 fixed.
// Template: BN (64/128), BKt (32/64), STAGES (1/2), ASRC, EPI.
// ASRC: 0 = pre-split planes, cp.async staged; 1 = fp32 A (ctx): scale by
//       g_inv, write back normalized, split (single A buffer).
// EPI:  0 = +bias -> split planes; 1 = exp/mask + row partials -> fp32;
//       2 = split planes; 3 = +bias -> fp32
// ---------------------------------------------------------------------------
template <int BN, int BKt, int STAGES, int ASRC, int EPI>
__global__ __launch_bounds__(256, 2) void mm_kernel(
    const ushortT* __restrict__ Ahp, const ushortT* __restrict__ Alp,
    const float* __restrict__ Af, float* __restrict__ Awb,
    const ushortT* __restrict__ Bhp, const ushortT* __restrict__ Blp,
    float* __restrict__ Cf, ushortT* __restrict__ Ch, ushortT* __restrict__ Cl,
    const float* __restrict__ bias,
    int nt, int lda, int ldb, int ldc,
    long sbA, long shA, long sbB, long shB, long sbC, long shC) {
    constexpr int KP  = BKt + 8;
    constexpr int APB = 128 * KP * 2;           // bytes per A plane buffer
    constexpr int BPB = BN * KP * 2;
    constexpr int ABUF = (ASRC == 0) ? STAGES : 1;
    constexpr int CPR = BKt / 8;                // 16B chunks per row
    constexpr int ACH = CPR / 2;                // A chunk iters (128 rows)
    constexpr int BCH = BN * CPR / 256;
    constexpr int KS  = BKt / 16;
    constexpr int NW  = BN / 32;
    constexpr int N8  = BN / 16;
    constexpr int oAl = ABUF * APB;
    constexpr int oBh = 2 * ABUF * APB;
    constexpr int oBl = oBh + STAGES * BPB;
    constexpr int WAITN = (STAGES >= 2) ? STAGES - 2 : 0;

    extern __shared__ char smem[];
    const unsigned sbase = (unsigned)__cvta_generic_to_shared(smem);
    float* rsum2 = (float*)(smem + oBl + STAGES * BPB);

    const int t = threadIdx.x, lane = t & 31, warp = t >> 5;
    const int wm = (warp >> 1) * 32, wn = (warp & 1) * (BN / 2);
    const int z = blockIdx.z;
    const long aoff = (long)(z / Hdim) * sbA + (long)(z % Hdim) * shA;
    const long boff = (long)(z / Hdim) * sbB + (long)(z % Hdim) * shB;
    const long coff = (long)(z / Hdim) * sbC + (long)(z % Hdim) * shC;
    const int row0 = blockIdx.y * 128, col0 = blockIdx.x * BN;
    const int lr = lane & 7, lhi = (lane >> 3) & 1, lk = lane >> 4;

    float acc[2][N8][4] = {};

    auto issueA = [&](int s, int kk) {
#pragma unroll
        for (int j = 0; j < ACH; ++j) {
            const int o = j * 256 + t, r = o / CPR, c = o % CPR;
            const unsigned d = sbase + s * APB + (unsigned)(r * KP + c * 8) * 2;
            const size_t g = aoff + (size_t)(row0 + r) * lda + kk + c * 8;
            cpasync16(d, &Ahp[g]);
            cpasync16(d + oAl, &Alp[g]);
        }
    };
    auto issueB = [&](int s, int kk) {
#pragma unroll
        for (int j = 0; j < BCH; ++j) {
            const int o = j * 256 + t, r = o / CPR, c = o % CPR;
            const unsigned d = sbase + oBh + s * BPB + (unsigned)(r * KP + c * 8) * 2;
            const size_t g = boff + (size_t)(col0 + r) * ldb + kk + c * 8;
            cpasync16(d, &Bhp[g]);
            cpasync16(d + STAGES * BPB, &Blp[g]);
        }
    };
    auto compute = [&](int sA, int sB) {
#pragma unroll
        for (int ks = 0; ks < KS; ++ks) {
            unsigned ah[2][4], al[2][4];
#pragma unroll
            for (int mi = 0; mi < 2; ++mi) {
                const unsigned ad = sbase + sA * APB +
                    (unsigned)((wm + mi * 16 + lr + lhi * 8) * KP + ks * 16 + lk * 8) * 2;
                ldmx4(ah[mi], ad);
                ldmx4(al[mi], ad + oAl);
            }
#pragma unroll
            for (int ni = 0; ni < NW; ++ni) {
                const unsigned bd = sbase + oBh + sB * BPB +
                    (unsigned)((wn + ni * 16 + lr + lhi * 8) * KP + ks * 16 + lk * 8) * 2;
                unsigned rh[4], rl[4];
                ldmx4(rh, bd);
                ldmx4(rl, bd + STAGES * BPB);
#pragma unroll
                for (int mi = 0; mi < 2; ++mi) {
                    mma_bf16(acc[mi][ni * 2],     ah[mi], rh[0], rh[2]);
                    mma_bf16(acc[mi][ni * 2 + 1], ah[mi], rh[1], rh[3]);
                    mma_bf16(acc[mi][ni * 2],     ah[mi], rl[0], rl[2]);
                    mma_bf16(acc[mi][ni * 2 + 1], ah[mi], rl[1], rl[3]);
                    mma_bf16(acc[mi][ni * 2],     al[mi], rh[0], rh[2]);
                    mma_bf16(acc[mi][ni * 2 + 1], al[mi], rh[1], rh[3]);
                }
            }
        }
    };

    if (ASRC == 0) {
        if (STAGES == 1) {
            for (int i = 0; i < nt; ++i) {
                if (i > 0) __syncthreads();
                issueA(0, i * BKt); issueB(0, i * BKt); cpcommit();
                cpwait<0>();
                __syncthreads();
                compute(0, 0);
            }
        } else {
#pragma unroll 1
            for (int s = 0; s < STAGES - 1 && s < nt; ++s) {
                issueA(s, s * BKt); issueB(s, s * BKt); cpcommit();
            }
            for (int i = 0; i < nt; ++i) {
                cpwait<WAITN>();
                __syncthreads();
                const int nx = i + STAGES - 1;
                if (nx < nt) { issueA(nx % STAGES, nx * BKt); issueB(nx % STAGES, nx * BKt); }
                cpcommit();
                compute(i % STAGES, i % STAGES);
            }
        }
    } else {
        // ctx path: STAGES==2 for B, single fp32-A buffer with reg prefetch
        const int ar = t >> 1, ac0 = (t & 1) * 16;
        const float invv = g_inv[(size_t)z * Sdim + row0 + ar];
        float4 areg[4];
#pragma unroll
        for (int q4 = 0; q4 < 4; ++q4)
            areg[q4] = *reinterpret_cast<const float4*>(
                &Af[aoff + (size_t)(row0 + ar) * lda + ac0 + q4 * 4]);
        issueB(0, 0); cpcommit();
        for (int i = 0; i < nt; ++i) {
            const int nx = i + 1;
            if (nx < nt) issueB(nx & 1, nx * BKt);
            cpcommit();
            // scale, write back normalized attn, split into As buffer 0
            const size_t gb = aoff + (size_t)(row0 + ar) * lda + i * BKt + ac0;
#pragma unroll
            for (int q4 = 0; q4 < 4; ++q4) {
                float4 v = areg[q4];
                v.x *= invv; v.y *= invv; v.z *= invv; v.w *= invv;
                *reinterpret_cast<float4*>(&Awb[gb + q4 * 4]) = v;
                ushortT h[4], l[4];
                split_bf(v.x, h[0], l[0]); split_bf(v.y, h[1], l[1]);
                split_bf(v.z, h[2], l[2]); split_bf(v.w, h[3], l[3]);
                const unsigned off = (unsigned)(ar * KP + ac0 + q4 * 4) * 2;
                *reinterpret_cast<uint2*>(smem + off)       = *reinterpret_cast<uint2*>(h);
                *reinterpret_cast<uint2*>(smem + off + oAl) = *reinterpret_cast<uint2*>(l);
            }
            if (nx < nt) {
#pragma unroll
                for (int q4 = 0; q4 < 4; ++q4)
                    areg[q4] = *reinterpret_cast<const float4*>(
                        &Af[aoff + (size_t)(row0 + ar) * lda + nx * BKt + ac0 + q4 * 4]);
            }
            cpwait<1>();
            __syncthreads();
            compute(0, i & 1);
            __syncthreads();
        }
    }

    // ---- epilogue ----
    const int maskbase = (z / Hdim) * Sdim;
#pragma unroll
    for (int mi = 0; mi < 2; ++mi)
#pragma unroll
        for (int n8 = 0; n8 < N8; ++n8) {
            const int rl0 = wm + mi * 16 + (lane >> 2);
            const int cl0 = wn + n8 * 8 + (lane & 3) * 2;
#pragma unroll
            for (int hf = 0; hf < 2; ++hf) {
                const int r = row0 + rl0 + hf * 8;
                const int c = col0 + cl0;
                float v0 = acc[mi][n8][hf * 2], v1 = acc[mi][n8][hf * 2 + 1];
                if (EPI == 0 || EPI == 3) { v0 += bias[c]; v1 += bias[c + 1]; }
                if (EPI == 1) {
                    v0 = g_mask[maskbase + c]     ? __expf(v0 * 0.125f) : 0.0f;
                    v1 = g_mask[maskbase + c + 1] ? __expf(v1 * 0.125f) : 0.0f;
                    acc[mi][n8][hf * 2] = v0; acc[mi][n8][hf * 2 + 1] = v1;
                }
                const size_t ci = coff + (size_t)r * ldc + c;
                if (EPI == 1 || EPI == 3) {
                    *reinterpret_cast<float2*>(&Cf[ci]) = make_float2(v0, v1);
                } else {
                    ushortT h0, l0, h1, l1;
                    split_bf(v0, h0, l0); split_bf(v1, h1, l1);
                    *reinterpret_cast<unsigned*>(&Ch[ci]) = (unsigned)h0 | ((unsigned)h1 << 16);
                    *reinterpret_cast<unsigned*>(&Cl[ci]) = (unsigned)l0 | ((unsigned)l1 << 16);
                }
            }
        }

    if (EPI == 1) {
#pragma unroll
        for (int mi = 0; mi < 2; ++mi)
#pragma unroll
            for (int hf = 0; hf < 2; ++hf) {
                float s = 0.0f;
#pragma unroll
                for (int n8 = 0; n8 < N8; ++n8)
                    s += acc[mi][n8][hf * 2] + acc[mi][n8][hf * 2 + 1];
                s += __shfl_xor_sync(0xFFFFFFFFu, s, 1);
                s += __shfl_xor_sync(0xFFFFFFFFu, s, 2);
                if ((lane & 3) == 0)
                    rsum2[(warp & 1) * 128 + wm + mi * 16 + (lane >> 2) + hf * 8] = s;
            }
        __syncthreads();
        if (t < 128) {
            float s = rsum2[t] + rsum2[128 + t];
            g_part[((size_t)z * Sdim + row0 + t) * 16 + blockIdx.x] = s;
        }
    }
}

// ---------------------------------------------------------------------------
extern "C" void kernel_launch(void* const* d_in, const int* in_sizes, int n_in,
                              void* d_out, int out_size) {
    const float* qs = (const float*)d_in[0];
    const float* ks = (const float*)d_in[1];
    const float* vs = (const float*)d_in[2];
    const void*  mk = d_in[3];
    const float* Wq = (const float*)d_in[4];
    const float* bq = (const float*)d_in[5];
    const float* Wk = (const float*)d_in[6];
    const float* bk = (const float*)d_in[7];
    const float* Wv = (const float*)d_in[8];
    const float* bv = (const float*)d_in[9];
    const float* Wo = (const float*)d_in[10];
    const float* bo = (const float*)d_in[11];

    float* out  = (float*)d_out;
    float* attn = out + (size_t)NROWS * Ddim;  // (out, attn) concatenated

    ushortT *iqh, *iql, *ikh, *ikl, *ivh, *ivl, *qh, *ql, *kh, *kl,
            *vh, *vl, *vth, *vtl, *wh, *wl, *ch, *cl;
    cudaGetSymbolAddress((void**)&iqh, g_iqh); cudaGetSymbolAddress((void**)&iql, g_iql);
    cudaGetSymbolAddress((void**)&ikh, g_ikh); cudaGetSymbolAddress((void**)&ikl, g_ikl);
    cudaGetSymbolAddress((void**)&ivh, g_ivh); cudaGetSymbolAddress((void**)&ivl, g_ivl);
    cudaGetSymbolAddress((void**)&qh,  g_qh);  cudaGetSymbolAddress((void**)&ql,  g_ql);
    cudaGetSymbolAddress((void**)&kh,  g_kh);  cudaGetSymbolAddress((void**)&kl,  g_kl);
    cudaGetSymbolAddress((void**)&vh,  g_vh);  cudaGetSymbolAddress((void**)&vl,  g_vl);
    cudaGetSymbolAddress((void**)&vth, g_vth); cudaGetSymbolAddress((void**)&vtl, g_vtl);
    cudaGetSymbolAddress((void**)&wh,  g_wh);  cudaGetSymbolAddress((void**)&wl,  g_wl);
    cudaGetSymbolAddress((void**)&ch,  g_ch);  cudaGetSymbolAddress((void**)&cl,  g_cl);

    const long SS = (long)Sdim * Sdim;
    const long SD = (long)Sdim * Ddim;
    const size_t WSZ = (size_t)Ddim * Ddim;
    dim3 blk(256);

    // smem bytes: 2*ABUF*APB + 2*STAGES*BPB (+1024 rsum when EPI==1)
    const int SM_PROJ = 2 * 2 * (128 * 40 * 2) + 2 * 2 * (128 * 40 * 2);            // 81920
    const int SM_SC   = 2 * 1 * (128 * 72 * 2) + 2 * 1 * (128 * 72 * 2) + 1024;     // 74752
    const int SM_CTX  = 2 * 1 * (128 * 40 * 2) + 2 * 2 * (64 * 40 * 2);             // 40960
    cudaFuncSetAttribute(mm_kernel<128, 32, 2, 0, 0>, cudaFuncAttributeMaxDynamicSharedMemorySize, SM_PROJ);
    cudaFuncSetAttribute(mm_kernel<128, 64, 1, 0, 1>, cudaFuncAttributeMaxDynamicSharedMemorySize, SM_SC);
    cudaFuncSetAttribute(mm_kernel<64, 32, 2, 1, 2>,  cudaFuncAttributeMaxDynamicSharedMemorySize, SM_CTX);
    cudaFuncSetAttribute(mm_kernel<128, 32, 2, 0, 3>, cudaFuncAttributeMaxDynamicSharedMemorySize, SM_PROJ);

    mask_expand_kernel<<<1, 256>>>(mk);
    split_inputs_kernel<<<dim3(4096, 1, 3), blk>>>(qs, ks, vs);
    wtrans_kernel<<<dim3(32, 32, 4), blk>>>(Wq, Wk, Wv, Wo);

    // QKV projections (128x128 tiles)
    dim3 gproj(Ddim / 128, NROWS / 128, 1);  // (8, 32)
    mm_kernel<128, 32, 2, 0, 0><<<gproj, blk, SM_PROJ>>>(
        iqh, iql, nullptr, nullptr, wh + 0 * WSZ, wl + 0 * WSZ,
        nullptr, qh, ql, bq, 32, Ddim, Ddim, Ddim, 0, 0, 0, 0, 0, 0);
    mm_kernel<128, 32, 2, 0, 0><<<gproj, blk, SM_PROJ>>>(
        ikh, ikl, nullptr, nullptr, wh + 1 * WSZ, wl + 1 * WSZ,
        nullptr, kh, kl, bk, 32, Ddim, Ddim, Ddim, 0, 0, 0, 0, 0, 0);
    mm_kernel<128, 32, 2, 0, 0><<<gproj, blk, SM_PROJ>>>(
        ivh, ivl, nullptr, nullptr, wh + 2 * WSZ, wl + 2 * WSZ,
        nullptr, vh, vl, bv, 32, Ddim, Ddim, Ddim, 0, 0, 0, 0, 0, 0);

    vtrans_kernel<<<dim3(Sdim / 32, DHdim / 32, 32), blk>>>();

    // scores -> exp(masked) into attn + row partials (128x128 tile, one K shot)
    dim3 gsc(Sdim / 128, Sdim / 128, Bdim * Hdim);  // (16, 16, 32)
    mm_kernel<128, 64, 1, 0, 1><<<gsc, blk, SM_SC>>>(
        qh, ql, nullptr, nullptr, kh, kl, attn, nullptr, nullptr, nullptr,
        1, Ddim, Ddim, Sdim, SD, DHdim, SD, DHdim, 16 * SS, SS);

    rowsum_kernel<<<NROWS_A / 256, 256>>>();

    // ctx = softmax(attn) @ V ; normalizes attn in-place; emits ctx planes
    dim3 gctx(1, Sdim / 128, Bdim * Hdim);  // (1, 16, 32)
    mm_kernel<64, 32, 2, 1, 2><<<gctx, blk, SM_CTX>>>(
        nullptr, nullptr, attn, attn, vth, vtl, nullptr, ch, cl, nullptr,
        64, Sdim, Sdim, Ddim,
        16 * SS, SS, (long)16 * DHdim * Sdim, (long)DHdim * Sdim, SD, DHdim);

    // output projection -> fp32 out
    mm_kernel<128, 32, 2, 0, 3><<<gproj, blk, SM_PROJ>>>(
        ch, cl, nullptr, nullptr, wh + 3 * WSZ, wl + 3 * WSZ,
        out, nullptr, nullptr, bo, 32, Ddim, Ddim, Ddim, 0, 0, 0, 0, 0, 0);
}